// round 1
// baseline (speedup 1.0000x reference)
#include <cuda_runtime.h>
#include <math.h>
#include <stdint.h>

#define TOK 4096          // B*T
#define CH  1024          // C
#define NH  16            // heads
#define HS  64            // head size

static constexpr size_t SZ = (size_t)TOK * CH;

// scratch offsets (floats)
static constexpr size_t OFF_XR   = 0 * SZ;
static constexpr size_t OFF_XW   = 1 * SZ;
static constexpr size_t OFF_XK   = 2 * SZ;
static constexpr size_t OFF_XV   = 3 * SZ;
static constexpr size_t OFF_XA   = 4 * SZ;
static constexpr size_t OFF_XG   = 5 * SZ;
static constexpr size_t OFF_R    = 6 * SZ;
static constexpr size_t OFF_K    = 7 * SZ;
static constexpr size_t OFF_V    = 8 * SZ;
static constexpr size_t OFF_TW   = 9 * SZ;
static constexpr size_t OFF_TA   = 10 * SZ;
static constexpr size_t OFF_TV   = 11 * SZ;
static constexpr size_t OFF_GATE = 12 * SZ;
static constexpr size_t OFF_WDEC = 13 * SZ;
static constexpr size_t OFF_AKK  = 14 * SZ;
static constexpr size_t OFF_BKK  = 15 * SZ;
static constexpr size_t OFF_Y    = 16 * SZ;
static constexpr size_t OFF_YP   = 17 * SZ;
static constexpr size_t OFF_HW   = 18 * SZ;
static constexpr size_t OFF_HA   = OFF_HW + (size_t)TOK * 64;
static constexpr size_t OFF_HV   = OFF_HA + (size_t)TOK * 64;
static constexpr size_t OFF_HG   = OFF_HV + (size_t)TOK * 32;
static constexpr size_t TOTALF   = OFF_HG + (size_t)TOK * 160;

__device__ float g_buf[TOTALF];

// ---------------------------------------------------------------------------
// 1) token-shift mixes: xr..xg = x + m*(last_x - x)
// ---------------------------------------------------------------------------
__global__ void __launch_bounds__(256) mix_kernel(
    const float* __restrict__ x,
    const float* __restrict__ mr, const float* __restrict__ mw,
    const float* __restrict__ mk, const float* __restrict__ mv,
    const float* __restrict__ ma, const float* __restrict__ mg)
{
    int idx = blockIdx.x * 256 + threadIdx.x;      // < TOK*CH (4M, fits int)
    int c   = idx & (CH - 1);
    int row = idx >> 10;                            // token row 0..4095
    int t   = row & 1023;                           // position within batch
    float xv = x[idx];
    float lx = (t == 0) ? 0.f : x[idx - CH];
    float dx = lx - xv;
    g_buf[OFF_XR + idx] = fmaf(mr[c], dx, xv);
    g_buf[OFF_XW + idx] = fmaf(mw[c], dx, xv);
    g_buf[OFF_XK + idx] = fmaf(mk[c], dx, xv);
    g_buf[OFF_XV + idx] = fmaf(mv[c], dx, xv);
    g_buf[OFF_XA + idx] = fmaf(ma[c], dx, xv);
    g_buf[OFF_XG + idx] = fmaf(mg[c], dx, xv);
}

// ---------------------------------------------------------------------------
// 2) generic fp32 GEMM, 64x64 tile, BK=16, 256 threads, 4x4 per thread.
//    transB=1: C[m,n] = sum_k A[m,k] * B[n,k]   (B is [N,K] row-major)
//    transB=0: C[m,n] = sum_k A[m,k] * B[k,n]   (B is [K,N] row-major)
//    act: 0 none, 1 tanh, 2 sigmoid.
//    Requirements: M % 64 == 0, K % 16 == 0, N % 4 == 0 (guards for N%64).
// ---------------------------------------------------------------------------
__global__ void __launch_bounds__(256) gemm_kernel(
    const float* __restrict__ A, const float* __restrict__ B,
    float* __restrict__ Cm, int M, int Nn, int K, int transB, int act)
{
    __shared__ float As[16][68];
    __shared__ float Bs[16][68];
    const int tid = threadIdx.x;
    const int tm = tid >> 4, tn = tid & 15;
    const int m0 = blockIdx.y * 64, n0 = blockIdx.x * 64;

    const int lm = tid >> 2;         // 0..63
    const int lk = (tid & 3) * 4;    // 0,4,8,12

    float acc[4][4];
#pragma unroll
    for (int i = 0; i < 4; i++)
#pragma unroll
        for (int j = 0; j < 4; j++) acc[i][j] = 0.f;

    for (int k0 = 0; k0 < K; k0 += 16) {
        // A tile
        float4 av = *(const float4*)(A + (size_t)(m0 + lm) * K + k0 + lk);
        As[lk + 0][lm] = av.x; As[lk + 1][lm] = av.y;
        As[lk + 2][lm] = av.z; As[lk + 3][lm] = av.w;
        // B tile
        if (transB) {
            int n = n0 + lm;
            float4 bv = make_float4(0.f, 0.f, 0.f, 0.f);
            if (n < Nn) bv = *(const float4*)(B + (size_t)n * K + k0 + lk);
            Bs[lk + 0][lm] = bv.x; Bs[lk + 1][lm] = bv.y;
            Bs[lk + 2][lm] = bv.z; Bs[lk + 3][lm] = bv.w;
        } else {
            int kk = tid >> 4;            // 0..15
            int nj = (tid & 15) * 4;      // 0..60
            int n  = n0 + nj;
            float4 bv;
            if (n + 3 < Nn) {
                bv = *(const float4*)(B + (size_t)(k0 + kk) * Nn + n);
            } else {
                float e0 = (n + 0 < Nn) ? B[(size_t)(k0 + kk) * Nn + n + 0] : 0.f;
                float e1 = (n + 1 < Nn) ? B[(size_t)(k0 + kk) * Nn + n + 1] : 0.f;
                float e2 = (n + 2 < Nn) ? B[(size_t)(k0 + kk) * Nn + n + 2] : 0.f;
                float e3 = (n + 3 < Nn) ? B[(size_t)(k0 + kk) * Nn + n + 3] : 0.f;
                bv = make_float4(e0, e1, e2, e3);
            }
            *(float4*)&Bs[kk][nj] = bv;
        }
        __syncthreads();
#pragma unroll
        for (int k = 0; k < 16; k++) {
            float4 a = *(const float4*)&As[k][tm * 4];
            float4 b = *(const float4*)&Bs[k][tn * 4];
            float ar[4] = {a.x, a.y, a.z, a.w};
            float br[4] = {b.x, b.y, b.z, b.w};
#pragma unroll
            for (int i = 0; i < 4; i++)
#pragma unroll
                for (int j = 0; j < 4; j++)
                    acc[i][j] = fmaf(ar[i], br[j], acc[i][j]);
        }
        __syncthreads();
    }

#pragma unroll
    for (int i = 0; i < 4; i++) {
        int row = m0 + tm * 4 + i;
#pragma unroll
        for (int j = 0; j < 4; j++) {
            int col = n0 + tn * 4 + j;
            if (col < Nn) {
                float v = acc[i][j];
                if (act == 1)      v = tanhf(v);
                else if (act == 2) v = 1.f / (1.f + expf(-v));
                Cm[(size_t)row * Nn + col] = v;
            }
        }
    }
}

// ---------------------------------------------------------------------------
// 3) per-channel epilogue of the LoRAs + kk normalization.
//    one warp per (token, head); each lane handles 2 channels.
// ---------------------------------------------------------------------------
__global__ void __launch_bounds__(256) ew_kernel(
    const float* __restrict__ v_first,
    const float* __restrict__ w0, const float* __restrict__ a0,
    const float* __restrict__ v0p, const float* __restrict__ k_k,
    const float* __restrict__ k_a)
{
    int wid  = blockIdx.x * 8 + (threadIdx.x >> 5);   // 0 .. TOK*NH-1
    int lane = threadIdx.x & 31;
    int t = wid >> 4;
    int h = wid & 15;
    int c0 = h * HS + lane * 2;
    size_t base = (size_t)t * CH + c0;

    float2 tw = *(const float2*)(g_buf + OFF_TW + base);
    float2 ta = *(const float2*)(g_buf + OFF_TA + base);
    float2 tv = *(const float2*)(g_buf + OFF_TV + base);
    float2 kv = *(const float2*)(g_buf + OFF_K + base);
    float2 vv = *(const float2*)(g_buf + OFF_V + base);
    float2 vf = *(const float2*)(v_first + base);
    float2 w0v  = *(const float2*)(w0 + c0);
    float2 a0v  = *(const float2*)(a0 + c0);
    float2 v0v  = *(const float2*)(v0p + c0);
    float2 kkv  = *(const float2*)(k_k + c0);
    float2 kav  = *(const float2*)(k_a + c0);

    // w decay
    auto decay = [](float w0c, float twc) {
        float z = -w0c - twc;
        float sp = (z > 20.f) ? z : log1pf(expf(z));
        float w = -sp - 0.5f;
        return expf(-expf(w));
    };
    float wd0 = decay(w0v.x, tw.x), wd1 = decay(w0v.y, tw.y);

    float aa0 = 1.f / (1.f + expf(-(a0v.x + ta.x)));
    float aa1 = 1.f / (1.f + expf(-(a0v.y + ta.y)));

    float sv0 = 1.f / (1.f + expf(-(v0v.x + tv.x)));
    float sv1 = 1.f / (1.f + expf(-(v0v.y + tv.y)));
    float nv0 = vv.x + (vf.x - vv.x) * sv0;
    float nv1 = vv.y + (vf.y - vv.y) * sv1;

    float kk0 = kv.x * kkv.x, kk1 = kv.y * kkv.y;
    float kn0 = kv.x * (1.f + (aa0 - 1.f) * kav.x);
    float kn1 = kv.y * (1.f + (aa1 - 1.f) * kav.y);

    float ss = kk0 * kk0 + kk1 * kk1;
#pragma unroll
    for (int m = 16; m; m >>= 1) ss += __shfl_xor_sync(0xffffffffu, ss, m);
    float inv = 1.f / fmaxf(sqrtf(ss), 1e-12f);
    float ak0 = kk0 * inv, ak1 = kk1 * inv;
    float bk0 = -ak0 * aa0, bk1 = -ak1 * aa1;

    *(float2*)(g_buf + OFF_WDEC + base) = make_float2(wd0, wd1);
    *(float2*)(g_buf + OFF_V    + base) = make_float2(nv0, nv1);
    *(float2*)(g_buf + OFF_K    + base) = make_float2(kn0, kn1);
    *(float2*)(g_buf + OFF_AKK  + base) = make_float2(ak0, ak1);
    *(float2*)(g_buf + OFF_BKK  + base) = make_float2(bk0, bk1);
}

// ---------------------------------------------------------------------------
// 4) recurrence. 256 CTAs: (b,h) pair * 4 row-groups. 128 threads:
//    16 rows x 8 column-lanes; each thread keeps 8 state floats in regs.
//    16-step chunks of r/w/k/v/a/b staged through shared memory.
// ---------------------------------------------------------------------------
__global__ void __launch_bounds__(128) rec_kernel()
{
    const int bh = blockIdx.x >> 2;   // 0..63
    const int rg = blockIdx.x & 3;
    const int b  = bh >> 4;
    const int h  = bh & 15;
    const int tid = threadIdx.x;
    const int rl = tid >> 3;          // 0..15 row in group
    const int q  = tid & 7;           // 0..7 column octet
    const int i  = rg * 16 + rl;      // state row 0..63
    const int j0 = q * 8;             // first state column

    __shared__ float sh[6][16][64];   // r,w,k,v,a,b  x 16 steps x 64

    const size_t base = ((size_t)b * 1024) * CH + (size_t)h * HS;
    const float* pr = g_buf + OFF_R    + base;
    const float* pw = g_buf + OFF_WDEC + base;
    const float* pk = g_buf + OFF_K    + base;
    const float* pv = g_buf + OFF_V    + base;
    const float* pa = g_buf + OFF_AKK  + base;
    const float* pb = g_buf + OFF_BKK  + base;
    float*       py = g_buf + OFF_Y    + base;

    float s[8];
#pragma unroll
    for (int jj = 0; jj < 8; jj++) s[jj] = 0.f;

    for (int t0 = 0; t0 < 1024; t0 += 16) {
        __syncthreads();   // previous chunk's compute done before overwrite
#pragma unroll
        for (int arr = 0; arr < 6; arr++) {
            const float* src = (arr == 0) ? pr : (arr == 1) ? pw :
                               (arr == 2) ? pk : (arr == 3) ? pv :
                               (arr == 4) ? pa : pb;
#pragma unroll
            for (int rr = 0; rr < 2; rr++) {
                int idx = tid + 128 * rr;     // 0..255  (16 steps x 16 float4)
                int st = idx >> 4;
                int sg = idx & 15;
                *(float4*)&sh[arr][st][sg * 4] =
                    *(const float4*)(src + (size_t)(t0 + st) * CH + sg * 4);
            }
        }
        __syncthreads();

        for (int tt = 0; tt < 16; tt++) {
            float4 a4a = *(const float4*)&sh[4][tt][j0];
            float4 a4b = *(const float4*)&sh[4][tt][j0 + 4];
            float a_[8] = {a4a.x, a4a.y, a4a.z, a4a.w, a4b.x, a4b.y, a4b.z, a4b.w};

            float sa0 = fmaf(s[0], a_[0], fmaf(s[2], a_[2], fmaf(s[4], a_[4], s[6] * a_[6])));
            float sa1 = fmaf(s[1], a_[1], fmaf(s[3], a_[3], fmaf(s[5], a_[5], s[7] * a_[7])));
            float sa = sa0 + sa1;
            sa += __shfl_xor_sync(0xffffffffu, sa, 1);
            sa += __shfl_xor_sync(0xffffffffu, sa, 2);
            sa += __shfl_xor_sync(0xffffffffu, sa, 4);

            float vi = sh[3][tt][i];

            float4 w4a = *(const float4*)&sh[1][tt][j0];
            float4 w4b = *(const float4*)&sh[1][tt][j0 + 4];
            float4 k4a = *(const float4*)&sh[2][tt][j0];
            float4 k4b = *(const float4*)&sh[2][tt][j0 + 4];
            float4 b4a = *(const float4*)&sh[5][tt][j0];
            float4 b4b = *(const float4*)&sh[5][tt][j0 + 4];
            float4 r4a = *(const float4*)&sh[0][tt][j0];
            float4 r4b = *(const float4*)&sh[0][tt][j0 + 4];
            float w_[8] = {w4a.x, w4a.y, w4a.z, w4a.w, w4b.x, w4b.y, w4b.z, w4b.w};
            float k_[8] = {k4a.x, k4a.y, k4a.z, k4a.w, k4b.x, k4b.y, k4b.z, k4b.w};
            float b_[8] = {b4a.x, b4a.y, b4a.z, b4a.w, b4b.x, b4b.y, b4b.z, b4b.w};
            float r_[8] = {r4a.x, r4a.y, r4a.z, r4a.w, r4b.x, r4b.y, r4b.z, r4b.w};

            float y0 = 0.f, y1 = 0.f;
#pragma unroll
            for (int jj = 0; jj < 8; jj++) {
                float ns = fmaf(sa, b_[jj], fmaf(vi, k_[jj], s[jj] * w_[jj]));
                s[jj] = ns;
                if (jj & 1) y1 = fmaf(ns, r_[jj], y1);
                else        y0 = fmaf(ns, r_[jj], y0);
            }
            float y = y0 + y1;
            y += __shfl_xor_sync(0xffffffffu, y, 1);
            y += __shfl_xor_sync(0xffffffffu, y, 2);
            y += __shfl_xor_sync(0xffffffffu, y, 4);
            if (q == 0) py[(size_t)(t0 + tt) * CH + i] = y;
        }
    }
}

// ---------------------------------------------------------------------------
// 5) GroupNorm + bonus + gate. one warp per (token, head).
// ---------------------------------------------------------------------------
__global__ void __launch_bounds__(256) post_kernel(
    const float* __restrict__ r_k,
    const float* __restrict__ gn_w, const float* __restrict__ gn_b)
{
    int wid  = blockIdx.x * 8 + (threadIdx.x >> 5);
    int lane = threadIdx.x & 31;
    int t = wid >> 4;
    int h = wid & 15;
    int c0 = h * HS + lane * 2;
    size_t base = (size_t)t * CH + c0;

    float2 yv = *(const float2*)(g_buf + OFF_Y + base);
    float2 rv = *(const float2*)(g_buf + OFF_R + base);
    float2 kv = *(const float2*)(g_buf + OFF_K + base);
    float2 vv = *(const float2*)(g_buf + OFF_V + base);
    float2 gv = *(const float2*)(g_buf + OFF_GATE + base);
    float2 rk = *(const float2*)(r_k + c0);

    float s1 = yv.x + yv.y;
    float s2 = yv.x * yv.x + yv.y * yv.y;
    float s3 = rv.x * kv.x * rk.x + rv.y * kv.y * rk.y;
#pragma unroll
    for (int m = 16; m; m >>= 1) {
        s1 += __shfl_xor_sync(0xffffffffu, s1, m);
        s2 += __shfl_xor_sync(0xffffffffu, s2, m);
        s3 += __shfl_xor_sync(0xffffffffu, s3, m);
    }
    float mu  = s1 * (1.f / 64.f);
    float var = s2 * (1.f / 64.f) - mu * mu;
    float rstd = rsqrtf(var + 0.00064f);

    float2 gw = *(const float2*)(gn_w + c0);
    float2 gb = *(const float2*)(gn_b + c0);
    float o0 = (fmaf((yv.x - mu) * rstd, gw.x, gb.x) + s3 * vv.x) * gv.x;
    float o1 = (fmaf((yv.y - mu) * rstd, gw.y, gb.y) + s3 * vv.y) * gv.y;
    *(float2*)(g_buf + OFF_YP + base) = make_float2(o0, o1);
}

// ---------------------------------------------------------------------------
extern "C" void kernel_launch(void* const* d_in, const int* in_sizes, int n_in,
                              void* d_out, int out_size)
{
    (void)in_sizes; (void)n_in; (void)out_size;
    float* buf = nullptr;
    cudaGetSymbolAddress((void**)&buf, g_buf);

    const float* x    = (const float*)d_in[0];
    const float* vfir = (const float*)d_in[1];
    const float* x_r  = (const float*)d_in[2];
    const float* x_w  = (const float*)d_in[3];
    const float* x_k  = (const float*)d_in[4];
    const float* x_v  = (const float*)d_in[5];
    const float* x_a  = (const float*)d_in[6];
    const float* x_g  = (const float*)d_in[7];
    const float* w0   = (const float*)d_in[8];
    const float* w1   = (const float*)d_in[9];
    const float* w2   = (const float*)d_in[10];
    const float* a0   = (const float*)d_in[11];
    const float* a1   = (const float*)d_in[12];
    const float* a2   = (const float*)d_in[13];
    const float* v0p  = (const float*)d_in[14];
    const float* v1   = (const float*)d_in[15];
    const float* v2   = (const float*)d_in[16];
    const float* g1   = (const float*)d_in[17];
    const float* g2   = (const float*)d_in[18];
    const float* k_k  = (const float*)d_in[19];
    const float* k_a  = (const float*)d_in[20];
    const float* r_k  = (const float*)d_in[21];
    const float* W_r  = (const float*)d_in[22];
    const float* W_k  = (const float*)d_in[23];
    const float* W_v  = (const float*)d_in[24];
    const float* W_o  = (const float*)d_in[25];
    const float* gn_w = (const float*)d_in[26];
    const float* gn_b = (const float*)d_in[27];
    float* out = (float*)d_out;

    // 1) token-shift mixes
    mix_kernel<<<(int)(SZ / 256), 256>>>(x, x_r, x_w, x_k, x_v, x_a, x_g);

    auto G = [&](const float* A, const float* B, float* Cm,
                 int M, int Nn, int K, int tb, int act) {
        dim3 grid((Nn + 63) / 64, M / 64);
        gemm_kernel<<<grid, 256>>>(A, B, Cm, M, Nn, K, tb, act);
    };

    // 2) big projections  r/k/v = xr/xk/xv @ W^T
    G(buf + OFF_XR, W_r, buf + OFF_R, TOK, CH, CH, 1, 0);
    G(buf + OFF_XK, W_k, buf + OFF_K, TOK, CH, CH, 1, 0);
    G(buf + OFF_XV, W_v, buf + OFF_V, TOK, CH, CH, 1, 0);

    // 3) LoRA MLPs
    G(buf + OFF_XW, w1, buf + OFF_HW, TOK, 64, CH, 0, 1);     // tanh(xw@w1)
    G(buf + OFF_HW, w2, buf + OFF_TW, TOK, CH, 64, 0, 0);
    G(buf + OFF_XA, a1, buf + OFF_HA, TOK, 64, CH, 0, 0);
    G(buf + OFF_HA, a2, buf + OFF_TA, TOK, CH, 64, 0, 0);
    G(buf + OFF_XV, v1, buf + OFF_HV, TOK, 32, CH, 0, 0);
    G(buf + OFF_HV, v2, buf + OFF_TV, TOK, CH, 32, 0, 0);
    G(buf + OFF_XG, g1, buf + OFF_HG, TOK, 160, CH, 0, 2);    // sigmoid(xg@g1)
    G(buf + OFF_HG, g2, buf + OFF_GATE, TOK, CH, 160, 0, 0);

    // 4) per-channel epilogue + kk normalize
    ew_kernel<<<TOK * NH / 8, 256>>>(vfir, w0, a0, v0p, k_k, k_a);

    // 5) recurrence
    rec_kernel<<<256, 128>>>();

    // 6) groupnorm + bonus + gate
    post_kernel<<<TOK * NH / 8, 256>>>(r_k, gn_w, gn_b);

    // 7) output projection into d_out
    G(buf + OFF_YP, W_o, out, TOK, CH, CH, 1, 0);
}

// round 2
// speedup vs baseline: 1.8591x; 1.8591x over previous
#include <cuda_runtime.h>
#include <math.h>
#include <stdint.h>

#define TOK 4096          // B*T
#define CH  1024          // C
#define NH  16            // heads
#define HS  64            // head size

static constexpr size_t SZ = (size_t)TOK * CH;

// scratch offsets (floats)
static constexpr size_t OFF_XR   = 0 * SZ;
static constexpr size_t OFF_XW   = 1 * SZ;
static constexpr size_t OFF_XK   = 2 * SZ;
static constexpr size_t OFF_XV   = 3 * SZ;
static constexpr size_t OFF_XA   = 4 * SZ;
static constexpr size_t OFF_XG   = 5 * SZ;
static constexpr size_t OFF_R    = 6 * SZ;
static constexpr size_t OFF_K    = 7 * SZ;
static constexpr size_t OFF_V    = 8 * SZ;
static constexpr size_t OFF_TW   = 9 * SZ;
static constexpr size_t OFF_TA   = 10 * SZ;
static constexpr size_t OFF_TV   = 11 * SZ;
static constexpr size_t OFF_GATE = 12 * SZ;
static constexpr size_t OFF_WDEC = 13 * SZ;
static constexpr size_t OFF_AKK  = 14 * SZ;
static constexpr size_t OFF_BKK  = 15 * SZ;
static constexpr size_t OFF_Y    = 16 * SZ;
static constexpr size_t OFF_YP   = 17 * SZ;
static constexpr size_t OFF_H    = 18 * SZ;   // packed LoRA hidden [TOK][384]
static constexpr size_t OFF_WUP  = 19 * SZ;   // packed up weights [1024][384]
static constexpr size_t TOTALF   = 20 * SZ;

#define NUP 384   // packed up width: w 0-63 | a 64-127 | v 128-159 | pad | g 192-351 | pad

__device__ float g_buf[TOTALF];

// ---------------------------------------------------------------------------
// 1) token-shift mixes: xr..xg = x + m*(last_x - x)
// ---------------------------------------------------------------------------
__global__ void __launch_bounds__(256) mix_kernel(
    const float* __restrict__ x,
    const float* __restrict__ mr, const float* __restrict__ mw,
    const float* __restrict__ mk, const float* __restrict__ mv,
    const float* __restrict__ ma, const float* __restrict__ mg)
{
    int idx = blockIdx.x * 256 + threadIdx.x;
    int c   = idx & (CH - 1);
    int row = idx >> 10;
    int t   = row & 1023;
    float xv = x[idx];
    float lx = (t == 0) ? 0.f : x[idx - CH];
    float dx = lx - xv;
    g_buf[OFF_XR + idx] = fmaf(mr[c], dx, xv);
    g_buf[OFF_XW + idx] = fmaf(mw[c], dx, xv);
    g_buf[OFF_XK + idx] = fmaf(mk[c], dx, xv);
    g_buf[OFF_XV + idx] = fmaf(mv[c], dx, xv);
    g_buf[OFF_XA + idx] = fmaf(ma[c], dx, xv);
    g_buf[OFF_XG + idx] = fmaf(mg[c], dx, xv);
}

// ---------------------------------------------------------------------------
// pack up-proj weights into [1024][384] (k-major), 64-aligned segments
// ---------------------------------------------------------------------------
__global__ void __launch_bounds__(256) pack_up_kernel(
    const float* __restrict__ w1, const float* __restrict__ a1,
    const float* __restrict__ v1, const float* __restrict__ g1)
{
    int idx = blockIdx.x * 256 + threadIdx.x;   // < 1024*384
    if (idx >= 1024 * NUP) return;
    int k = idx / NUP;
    int n = idx - k * NUP;
    float v;
    if      (n < 64)  v = w1[k * 64  + n];
    else if (n < 128) v = a1[k * 64  + (n - 64)];
    else if (n < 160) v = v1[k * 32  + (n - 128)];
    else if (n < 192) v = 0.f;
    else if (n < 352) v = g1[k * 160 + (n - 192)];
    else              v = 0.f;
    g_buf[OFF_WUP + idx] = v;
}

// ---------------------------------------------------------------------------
// 2) tf32 tensor-core GEMM (transB): C[m,n] = sum_k A[m,k] * B[n,k]
//    128x128 tile, BK=16, 256 threads (8 warps, 2x4), warp tile 64x32.
//    Requires M%128==0, N%128==0, K%16==0.
// ---------------------------------------------------------------------------
__device__ __forceinline__ uint32_t f2tf32(float f) {
    uint32_t u; asm("cvt.rna.tf32.f32 %0, %1;" : "=r"(u) : "f"(f)); return u;
}

__global__ void __launch_bounds__(256) gemm_tf32_nt(
    const float* __restrict__ A, const float* __restrict__ B,
    float* __restrict__ Cm, int M, int Nn, int K)
{
    __shared__ uint32_t As[2][128][20];
    __shared__ uint32_t Bs[2][128][20];
    const int tid  = threadIdx.x;
    const int lane = tid & 31, warp = tid >> 5;
    const int wm = warp >> 2, wn = warp & 3;            // 2 x 4 warps
    const int m0 = blockIdx.y * 128, n0 = blockIdx.x * 128;

    const int lr = tid >> 2;            // 0..63
    const int lc = (tid & 3) * 4;       // 0,4,8,12

    const float* Aptr = A + (size_t)(m0 + lr) * K + lc;
    const float* Bptr = B + (size_t)(n0 + lr) * K + lc;

    float acc[4][4][4];
#pragma unroll
    for (int mt = 0; mt < 4; mt++)
#pragma unroll
        for (int nt = 0; nt < 4; nt++)
#pragma unroll
            for (int r = 0; r < 4; r++) acc[mt][nt][r] = 0.f;

    // preload k0 = 0
    {
        float4 a0 = *(const float4*)(Aptr);
        float4 a1 = *(const float4*)(Aptr + (size_t)64 * K);
        float4 b0 = *(const float4*)(Bptr);
        float4 b1 = *(const float4*)(Bptr + (size_t)64 * K);
        As[0][lr][lc+0] = f2tf32(a0.x); As[0][lr][lc+1] = f2tf32(a0.y);
        As[0][lr][lc+2] = f2tf32(a0.z); As[0][lr][lc+3] = f2tf32(a0.w);
        As[0][lr+64][lc+0] = f2tf32(a1.x); As[0][lr+64][lc+1] = f2tf32(a1.y);
        As[0][lr+64][lc+2] = f2tf32(a1.z); As[0][lr+64][lc+3] = f2tf32(a1.w);
        Bs[0][lr][lc+0] = f2tf32(b0.x); Bs[0][lr][lc+1] = f2tf32(b0.y);
        Bs[0][lr][lc+2] = f2tf32(b0.z); Bs[0][lr][lc+3] = f2tf32(b0.w);
        Bs[0][lr+64][lc+0] = f2tf32(b1.x); Bs[0][lr+64][lc+1] = f2tf32(b1.y);
        Bs[0][lr+64][lc+2] = f2tf32(b1.z); Bs[0][lr+64][lc+3] = f2tf32(b1.w);
    }
    __syncthreads();

    int buf = 0;
    for (int k0 = 0; k0 < K; k0 += 16) {
        float4 na0, na1, nb0, nb1;
        const bool more = (k0 + 16) < K;
        if (more) {
            na0 = *(const float4*)(Aptr + k0 + 16);
            na1 = *(const float4*)(Aptr + (size_t)64 * K + k0 + 16);
            nb0 = *(const float4*)(Bptr + k0 + 16);
            nb1 = *(const float4*)(Bptr + (size_t)64 * K + k0 + 16);
        }
#pragma unroll
        for (int kk = 0; kk < 2; kk++) {
            uint32_t af[4][4], bf[4][2];
            const int c = kk * 8 + (lane & 3);
#pragma unroll
            for (int mt = 0; mt < 4; mt++) {
                int r = wm * 64 + mt * 16 + (lane >> 2);
                af[mt][0] = As[buf][r    ][c];
                af[mt][1] = As[buf][r + 8][c];
                af[mt][2] = As[buf][r    ][c + 4];
                af[mt][3] = As[buf][r + 8][c + 4];
            }
#pragma unroll
            for (int nt = 0; nt < 4; nt++) {
                int n = wn * 32 + nt * 8 + (lane >> 2);
                bf[nt][0] = Bs[buf][n][c];
                bf[nt][1] = Bs[buf][n][c + 4];
            }
#pragma unroll
            for (int mt = 0; mt < 4; mt++)
#pragma unroll
                for (int nt = 0; nt < 4; nt++) {
                    asm volatile(
                        "mma.sync.aligned.m16n8k8.row.col.f32.tf32.tf32.f32 "
                        "{%0,%1,%2,%3},{%4,%5,%6,%7},{%8,%9},{%0,%1,%2,%3};"
                        : "+f"(acc[mt][nt][0]), "+f"(acc[mt][nt][1]),
                          "+f"(acc[mt][nt][2]), "+f"(acc[mt][nt][3])
                        : "r"(af[mt][0]), "r"(af[mt][1]),
                          "r"(af[mt][2]), "r"(af[mt][3]),
                          "r"(bf[nt][0]), "r"(bf[nt][1]));
                }
        }
        if (more) {
            int nb = buf ^ 1;
            As[nb][lr][lc+0] = f2tf32(na0.x); As[nb][lr][lc+1] = f2tf32(na0.y);
            As[nb][lr][lc+2] = f2tf32(na0.z); As[nb][lr][lc+3] = f2tf32(na0.w);
            As[nb][lr+64][lc+0] = f2tf32(na1.x); As[nb][lr+64][lc+1] = f2tf32(na1.y);
            As[nb][lr+64][lc+2] = f2tf32(na1.z); As[nb][lr+64][lc+3] = f2tf32(na1.w);
            Bs[nb][lr][lc+0] = f2tf32(nb0.x); Bs[nb][lr][lc+1] = f2tf32(nb0.y);
            Bs[nb][lr][lc+2] = f2tf32(nb0.z); Bs[nb][lr][lc+3] = f2tf32(nb0.w);
            Bs[nb][lr+64][lc+0] = f2tf32(nb1.x); Bs[nb][lr+64][lc+1] = f2tf32(nb1.y);
            Bs[nb][lr+64][lc+2] = f2tf32(nb1.z); Bs[nb][lr+64][lc+3] = f2tf32(nb1.w);
        }
        __syncthreads();
        buf ^= 1;
    }

#pragma unroll
    for (int mt = 0; mt < 4; mt++) {
        int row = m0 + wm * 64 + mt * 16 + (lane >> 2);
#pragma unroll
        for (int nt = 0; nt < 4; nt++) {
            int col = n0 + wn * 32 + nt * 8 + (lane & 3) * 2;
            *(float2*)(Cm + (size_t)row * Nn + col) =
                make_float2(acc[mt][nt][0], acc[mt][nt][1]);
            *(float2*)(Cm + (size_t)(row + 8) * Nn + col) =
                make_float2(acc[mt][nt][2], acc[mt][nt][3]);
        }
    }
}

// ---------------------------------------------------------------------------
// 3) generic fp32 GEMM (kept for LoRA down-projections), 64x64 tile, BK=16.
//    transB=0 only here: C[m,n] = sum_k A[m,k]*B[k,n], A row stride = lda.
//    act: 0 none, 1 tanh, 2 sigmoid.
// ---------------------------------------------------------------------------
__global__ void __launch_bounds__(256) gemm_kernel(
    const float* __restrict__ A, const float* __restrict__ B,
    float* __restrict__ Cm, int M, int Nn, int K, int lda, int act)
{
    __shared__ float As[16][68];
    __shared__ float Bs[16][68];
    const int tid = threadIdx.x;
    const int tm = tid >> 4, tn = tid & 15;
    const int m0 = blockIdx.y * 64, n0 = blockIdx.x * 64;

    const int lm = tid >> 2;
    const int lk = (tid & 3) * 4;

    float acc[4][4];
#pragma unroll
    for (int i = 0; i < 4; i++)
#pragma unroll
        for (int j = 0; j < 4; j++) acc[i][j] = 0.f;

    for (int k0 = 0; k0 < K; k0 += 16) {
        float4 av = *(const float4*)(A + (size_t)(m0 + lm) * lda + k0 + lk);
        As[lk + 0][lm] = av.x; As[lk + 1][lm] = av.y;
        As[lk + 2][lm] = av.z; As[lk + 3][lm] = av.w;
        {
            int kk = tid >> 4;
            int nj = (tid & 15) * 4;
            float4 bv = *(const float4*)(B + (size_t)(k0 + kk) * Nn + n0 + nj);
            *(float4*)&Bs[kk][nj] = bv;
        }
        __syncthreads();
#pragma unroll
        for (int k = 0; k < 16; k++) {
            float4 a = *(const float4*)&As[k][tm * 4];
            float4 b = *(const float4*)&Bs[k][tn * 4];
            float ar[4] = {a.x, a.y, a.z, a.w};
            float br[4] = {b.x, b.y, b.z, b.w};
#pragma unroll
            for (int i = 0; i < 4; i++)
#pragma unroll
                for (int j = 0; j < 4; j++)
                    acc[i][j] = fmaf(ar[i], br[j], acc[i][j]);
        }
        __syncthreads();
    }

#pragma unroll
    for (int i = 0; i < 4; i++) {
        int row = m0 + tm * 4 + i;
#pragma unroll
        for (int j = 0; j < 4; j++) {
            int col = n0 + tn * 4 + j;
            float v = acc[i][j];
            if (act == 1)      v = tanhf(v);
            else if (act == 2) v = 1.f / (1.f + expf(-v));
            Cm[(size_t)row * Nn + col] = v;
        }
    }
}

// ---------------------------------------------------------------------------
// fused LoRA up-projection: H[TOK][384] = [xw@w1 | xa@a1 | xv@v1 | 0 | xg@g1 | 0]
// A pointer + activation selected per 64-wide column tile.
// ---------------------------------------------------------------------------
__global__ void __launch_bounds__(256) gemm_up_kernel(
    const float* __restrict__ Aw, const float* __restrict__ Aa,
    const float* __restrict__ Av, const float* __restrict__ Ag)
{
    __shared__ float As[16][68];
    __shared__ float Bs[16][68];
    const int tid = threadIdx.x;
    const int tm = tid >> 4, tn = tid & 15;
    const int m0 = blockIdx.y * 64, n0 = blockIdx.x * 64;

    const int seg = (blockIdx.x == 0) ? 0 : (blockIdx.x == 1) ? 1 :
                    (blockIdx.x == 2) ? 2 : 3;
    const float* A = (seg == 0) ? Aw : (seg == 1) ? Aa : (seg == 2) ? Av : Ag;
    const float* B = g_buf + OFF_WUP;
    float* Cm = g_buf + OFF_H;

    const int lm = tid >> 2;
    const int lk = (tid & 3) * 4;

    float acc[4][4];
#pragma unroll
    for (int i = 0; i < 4; i++)
#pragma unroll
        for (int j = 0; j < 4; j++) acc[i][j] = 0.f;

    for (int k0 = 0; k0 < CH; k0 += 16) {
        float4 av = *(const float4*)(A + (size_t)(m0 + lm) * CH + k0 + lk);
        As[lk + 0][lm] = av.x; As[lk + 1][lm] = av.y;
        As[lk + 2][lm] = av.z; As[lk + 3][lm] = av.w;
        {
            int kk = tid >> 4;
            int nj = (tid & 15) * 4;
            float4 bv = *(const float4*)(B + (size_t)(k0 + kk) * NUP + n0 + nj);
            *(float4*)&Bs[kk][nj] = bv;
        }
        __syncthreads();
#pragma unroll
        for (int k = 0; k < 16; k++) {
            float4 a = *(const float4*)&As[k][tm * 4];
            float4 b = *(const float4*)&Bs[k][tn * 4];
            float ar[4] = {a.x, a.y, a.z, a.w};
            float br[4] = {b.x, b.y, b.z, b.w};
#pragma unroll
            for (int i = 0; i < 4; i++)
#pragma unroll
                for (int j = 0; j < 4; j++)
                    acc[i][j] = fmaf(ar[i], br[j], acc[i][j]);
        }
        __syncthreads();
    }

#pragma unroll
    for (int i = 0; i < 4; i++) {
        int row = m0 + tm * 4 + i;
#pragma unroll
        for (int j = 0; j < 4; j++) {
            int col = n0 + tn * 4 + j;
            float v = acc[i][j];
            if (seg == 0)      v = tanhf(v);
            else if (seg == 3) v = 1.f / (1.f + expf(-v));
            Cm[(size_t)row * NUP + col] = v;
        }
    }
}

// ---------------------------------------------------------------------------
// 4) per-channel epilogue of the LoRAs + kk normalization.
// ---------------------------------------------------------------------------
__global__ void __launch_bounds__(256) ew_kernel(
    const float* __restrict__ v_first,
    const float* __restrict__ w0, const float* __restrict__ a0,
    const float* __restrict__ v0p, const float* __restrict__ k_k,
    const float* __restrict__ k_a)
{
    int wid  = blockIdx.x * 8 + (threadIdx.x >> 5);
    int lane = threadIdx.x & 31;
    int t = wid >> 4;
    int h = wid & 15;
    int c0 = h * HS + lane * 2;
    size_t base = (size_t)t * CH + c0;

    float2 tw = *(const float2*)(g_buf + OFF_TW + base);
    float2 ta = *(const float2*)(g_buf + OFF_TA + base);
    float2 tv = *(const float2*)(g_buf + OFF_TV + base);
    float2 kv = *(const float2*)(g_buf + OFF_K + base);
    float2 vv = *(const float2*)(g_buf + OFF_V + base);
    float2 vf = *(const float2*)(v_first + base);
    float2 w0v  = *(const float2*)(w0 + c0);
    float2 a0v  = *(const float2*)(a0 + c0);
    float2 v0v  = *(const float2*)(v0p + c0);
    float2 kkv  = *(const float2*)(k_k + c0);
    float2 kav  = *(const float2*)(k_a + c0);

    auto decay = [](float w0c, float twc) {
        float z = -w0c - twc;
        float sp = (z > 20.f) ? z : log1pf(expf(z));
        float w = -sp - 0.5f;
        return expf(-expf(w));
    };
    float wd0 = decay(w0v.x, tw.x), wd1 = decay(w0v.y, tw.y);

    float aa0 = 1.f / (1.f + expf(-(a0v.x + ta.x)));
    float aa1 = 1.f / (1.f + expf(-(a0v.y + ta.y)));

    float sv0 = 1.f / (1.f + expf(-(v0v.x + tv.x)));
    float sv1 = 1.f / (1.f + expf(-(v0v.y + tv.y)));
    float nv0 = vv.x + (vf.x - vv.x) * sv0;
    float nv1 = vv.y + (vf.y - vv.y) * sv1;

    float kk0 = kv.x * kkv.x, kk1 = kv.y * kkv.y;
    float kn0 = kv.x * (1.f + (aa0 - 1.f) * kav.x);
    float kn1 = kv.y * (1.f + (aa1 - 1.f) * kav.y);

    float ss = kk0 * kk0 + kk1 * kk1;
#pragma unroll
    for (int m = 16; m; m >>= 1) ss += __shfl_xor_sync(0xffffffffu, ss, m);
    float inv = 1.f / fmaxf(sqrtf(ss), 1e-12f);
    float ak0 = kk0 * inv, ak1 = kk1 * inv;
    float bk0 = -ak0 * aa0, bk1 = -ak1 * aa1;

    *(float2*)(g_buf + OFF_WDEC + base) = make_float2(wd0, wd1);
    *(float2*)(g_buf + OFF_V    + base) = make_float2(nv0, nv1);
    *(float2*)(g_buf + OFF_K    + base) = make_float2(kn0, kn1);
    *(float2*)(g_buf + OFF_AKK  + base) = make_float2(ak0, ak1);
    *(float2*)(g_buf + OFF_BKK  + base) = make_float2(bk0, bk1);
}

// ---------------------------------------------------------------------------
// 5) recurrence. 256 CTAs: (b,h) pair * 4 row-groups.
// ---------------------------------------------------------------------------
__global__ void __launch_bounds__(128) rec_kernel()
{
    const int bh = blockIdx.x >> 2;
    const int rg = blockIdx.x & 3;
    const int b  = bh >> 4;
    const int h  = bh & 15;
    const int tid = threadIdx.x;
    const int rl = tid >> 3;
    const int q  = tid & 7;
    const int i  = rg * 16 + rl;
    const int j0 = q * 8;

    __shared__ float sh[6][16][64];

    const size_t base = ((size_t)b * 1024) * CH + (size_t)h * HS;
    const float* pr = g_buf + OFF_R    + base;
    const float* pw = g_buf + OFF_WDEC + base;
    const float* pk = g_buf + OFF_K    + base;
    const float* pv = g_buf + OFF_V    + base;
    const float* pa = g_buf + OFF_AKK  + base;
    const float* pb = g_buf + OFF_BKK  + base;
    float*       py = g_buf + OFF_Y    + base;

    float s[8];
#pragma unroll
    for (int jj = 0; jj < 8; jj++) s[jj] = 0.f;

    for (int t0 = 0; t0 < 1024; t0 += 16) {
        __syncthreads();
#pragma unroll
        for (int arr = 0; arr < 6; arr++) {
            const float* src = (arr == 0) ? pr : (arr == 1) ? pw :
                               (arr == 2) ? pk : (arr == 3) ? pv :
                               (arr == 4) ? pa : pb;
#pragma unroll
            for (int rr = 0; rr < 2; rr++) {
                int idx = tid + 128 * rr;
                int st = idx >> 4;
                int sg = idx & 15;
                *(float4*)&sh[arr][st][sg * 4] =
                    *(const float4*)(src + (size_t)(t0 + st) * CH + sg * 4);
            }
        }
        __syncthreads();

        for (int tt = 0; tt < 16; tt++) {
            float4 a4a = *(const float4*)&sh[4][tt][j0];
            float4 a4b = *(const float4*)&sh[4][tt][j0 + 4];
            float a_[8] = {a4a.x, a4a.y, a4a.z, a4a.w, a4b.x, a4b.y, a4b.z, a4b.w};

            float sa0 = fmaf(s[0], a_[0], fmaf(s[2], a_[2], fmaf(s[4], a_[4], s[6] * a_[6])));
            float sa1 = fmaf(s[1], a_[1], fmaf(s[3], a_[3], fmaf(s[5], a_[5], s[7] * a_[7])));
            float sa = sa0 + sa1;
            sa += __shfl_xor_sync(0xffffffffu, sa, 1);
            sa += __shfl_xor_sync(0xffffffffu, sa, 2);
            sa += __shfl_xor_sync(0xffffffffu, sa, 4);

            float vi = sh[3][tt][i];

            float4 w4a = *(const float4*)&sh[1][tt][j0];
            float4 w4b = *(const float4*)&sh[1][tt][j0 + 4];
            float4 k4a = *(const float4*)&sh[2][tt][j0];
            float4 k4b = *(const float4*)&sh[2][tt][j0 + 4];
            float4 b4a = *(const float4*)&sh[5][tt][j0];
            float4 b4b = *(const float4*)&sh[5][tt][j0 + 4];
            float4 r4a = *(const float4*)&sh[0][tt][j0];
            float4 r4b = *(const float4*)&sh[0][tt][j0 + 4];
            float w_[8] = {w4a.x, w4a.y, w4a.z, w4a.w, w4b.x, w4b.y, w4b.z, w4b.w};
            float k_[8] = {k4a.x, k4a.y, k4a.z, k4a.w, k4b.x, k4b.y, k4b.z, k4b.w};
            float b_[8] = {b4a.x, b4a.y, b4a.z, b4a.w, b4b.x, b4b.y, b4b.z, b4b.w};
            float r_[8] = {r4a.x, r4a.y, r4a.z, r4a.w, r4b.x, r4b.y, r4b.z, r4b.w};

            float y0 = 0.f, y1 = 0.f;
#pragma unroll
            for (int jj = 0; jj < 8; jj++) {
                float ns = fmaf(sa, b_[jj], fmaf(vi, k_[jj], s[jj] * w_[jj]));
                s[jj] = ns;
                if (jj & 1) y1 = fmaf(ns, r_[jj], y1);
                else        y0 = fmaf(ns, r_[jj], y0);
            }
            float y = y0 + y1;
            y += __shfl_xor_sync(0xffffffffu, y, 1);
            y += __shfl_xor_sync(0xffffffffu, y, 2);
            y += __shfl_xor_sync(0xffffffffu, y, 4);
            if (q == 0) py[(size_t)(t0 + tt) * CH + i] = y;
        }
    }
}

// ---------------------------------------------------------------------------
// 6) GroupNorm + bonus + gate.
// ---------------------------------------------------------------------------
__global__ void __launch_bounds__(256) post_kernel(
    const float* __restrict__ r_k,
    const float* __restrict__ gn_w, const float* __restrict__ gn_b)
{
    int wid  = blockIdx.x * 8 + (threadIdx.x >> 5);
    int lane = threadIdx.x & 31;
    int t = wid >> 4;
    int h = wid & 15;
    int c0 = h * HS + lane * 2;
    size_t base = (size_t)t * CH + c0;

    float2 yv = *(const float2*)(g_buf + OFF_Y + base);
    float2 rv = *(const float2*)(g_buf + OFF_R + base);
    float2 kv = *(const float2*)(g_buf + OFF_K + base);
    float2 vv = *(const float2*)(g_buf + OFF_V + base);
    float2 gv = *(const float2*)(g_buf + OFF_GATE + base);
    float2 rk = *(const float2*)(r_k + c0);

    float s1 = yv.x + yv.y;
    float s2 = yv.x * yv.x + yv.y * yv.y;
    float s3 = rv.x * kv.x * rk.x + rv.y * kv.y * rk.y;
#pragma unroll
    for (int m = 16; m; m >>= 1) {
        s1 += __shfl_xor_sync(0xffffffffu, s1, m);
        s2 += __shfl_xor_sync(0xffffffffu, s2, m);
        s3 += __shfl_xor_sync(0xffffffffu, s3, m);
    }
    float mu  = s1 * (1.f / 64.f);
    float var = s2 * (1.f / 64.f) - mu * mu;
    float rstd = rsqrtf(var + 0.00064f);

    float2 gw = *(const float2*)(gn_w + c0);
    float2 gb = *(const float2*)(gn_b + c0);
    float o0 = (fmaf((yv.x - mu) * rstd, gw.x, gb.x) + s3 * vv.x) * gv.x;
    float o1 = (fmaf((yv.y - mu) * rstd, gw.y, gb.y) + s3 * vv.y) * gv.y;
    *(float2*)(g_buf + OFF_YP + base) = make_float2(o0, o1);
}

// ---------------------------------------------------------------------------
extern "C" void kernel_launch(void* const* d_in, const int* in_sizes, int n_in,
                              void* d_out, int out_size)
{
    (void)in_sizes; (void)n_in; (void)out_size;
    float* buf = nullptr;
    cudaGetSymbolAddress((void**)&buf, g_buf);

    const float* x    = (const float*)d_in[0];
    const float* vfir = (const float*)d_in[1];
    const float* x_r  = (const float*)d_in[2];
    const float* x_w  = (const float*)d_in[3];
    const float* x_k  = (const float*)d_in[4];
    const float* x_v  = (const float*)d_in[5];
    const float* x_a  = (const float*)d_in[6];
    const float* x_g  = (const float*)d_in[7];
    const float* w0   = (const float*)d_in[8];
    const float* w1   = (const float*)d_in[9];
    const float* w2   = (const float*)d_in[10];
    const float* a0   = (const float*)d_in[11];
    const float* a1   = (const float*)d_in[12];
    const float* a2   = (const float*)d_in[13];
    const float* v0p  = (const float*)d_in[14];
    const float* v1   = (const float*)d_in[15];
    const float* v2   = (const float*)d_in[16];
    const float* g1   = (const float*)d_in[17];
    const float* g2   = (const float*)d_in[18];
    const float* k_k  = (const float*)d_in[19];
    const float* k_a  = (const float*)d_in[20];
    const float* r_k  = (const float*)d_in[21];
    const float* W_r  = (const float*)d_in[22];
    const float* W_k  = (const float*)d_in[23];
    const float* W_v  = (const float*)d_in[24];
    const float* W_o  = (const float*)d_in[25];
    const float* gn_w = (const float*)d_in[26];
    const float* gn_b = (const float*)d_in[27];
    float* out = (float*)d_out;

    // 1) token-shift mixes + weight pack
    mix_kernel<<<(int)(SZ / 256), 256>>>(x, x_r, x_w, x_k, x_v, x_a, x_g);
    pack_up_kernel<<<(1024 * NUP + 255) / 256, 256>>>(w1, a1, v1, g1);

    // 2) big projections (tf32 tensor cores): r/k/v = xr/xk/xv @ W^T
    dim3 gBig(CH / 128, TOK / 128);
    gemm_tf32_nt<<<gBig, 256>>>(buf + OFF_XR, W_r, buf + OFF_R, TOK, CH, CH);
    gemm_tf32_nt<<<gBig, 256>>>(buf + OFF_XK, W_k, buf + OFF_K, TOK, CH, CH);
    gemm_tf32_nt<<<gBig, 256>>>(buf + OFF_XV, W_v, buf + OFF_V, TOK, CH, CH);

    // 3) fused LoRA up-projection -> H [TOK][384]
    gemm_up_kernel<<<dim3(NUP / 64, TOK / 64), 256>>>(
        buf + OFF_XW, buf + OFF_XA, buf + OFF_XV, buf + OFF_XG);

    // 4) LoRA down-projections (A = packed H, lda = 384)
    auto G = [&](const float* A, const float* B, float* Cm, int K) {
        gemm_kernel<<<dim3(CH / 64, TOK / 64), 256>>>(A, B, Cm, TOK, CH, K, NUP, 0);
    };
    G(buf + OFF_H + 0,   w2, buf + OFF_TW,   64);
    G(buf + OFF_H + 64,  a2, buf + OFF_TA,   64);
    G(buf + OFF_H + 128, v2, buf + OFF_TV,   32);
    G(buf + OFF_H + 192, g2, buf + OFF_GATE, 160);

    // 5) per-channel epilogue + kk normalize
    ew_kernel<<<TOK * NH / 8, 256>>>(vfir, w0, a0, v0p, k_k, k_a);

    // 6) recurrence
    rec_kernel<<<256, 128>>>();

    // 7) groupnorm + bonus + gate
    post_kernel<<<TOK * NH / 8, 256>>>(r_k, gn_w, gn_b);

    // 8) output projection (tf32) into d_out
    gemm_tf32_nt<<<gBig, 256>>>(buf + OFF_YP, W_o, out, TOK, CH, CH);
}

// round 4
// speedup vs baseline: 1.9697x; 1.0595x over previous
#include <cuda_runtime.h>
#include <math.h>
#include <stdint.h>

#define TOK 4096          // B*T
#define CH  1024          // C
#define NH  16            // heads
#define HS  64            // head size
#define NUP 384           // packed LoRA width: w 0-63 | a 64-127 | v 128-159 | pad | g 192-351 | pad

static constexpr size_t SZ = (size_t)TOK * CH;

static constexpr size_t OFF_XR   = 0 * SZ;
static constexpr size_t OFF_XW   = 1 * SZ;
static constexpr size_t OFF_XK   = 2 * SZ;
static constexpr size_t OFF_XV   = 3 * SZ;
static constexpr size_t OFF_XA   = 4 * SZ;
static constexpr size_t OFF_XG   = 5 * SZ;
static constexpr size_t OFF_R    = 6 * SZ;
static constexpr size_t OFF_K    = 7 * SZ;
static constexpr size_t OFF_V    = 8 * SZ;
static constexpr size_t OFF_TW   = 9 * SZ;    // TW,TA,TV,GATE contiguous (batched dn out)
static constexpr size_t OFF_TA   = 10 * SZ;
static constexpr size_t OFF_TV   = 11 * SZ;
static constexpr size_t OFF_GATE = 12 * SZ;
static constexpr size_t OFF_WDEC = 13 * SZ;
static constexpr size_t OFF_AKK  = 14 * SZ;
static constexpr size_t OFF_BKK  = 15 * SZ;
static constexpr size_t OFF_Y    = 16 * SZ;
static constexpr size_t OFF_YP   = 17 * SZ;
static constexpr size_t OFF_H    = 18 * SZ;                      // [TOK][384]
static constexpr size_t OFF_WUP  = 19 * SZ;                      // [1024][384] k-major (fp32 up)
static constexpr size_t OFF_WDNT = 19 * SZ + (size_t)512 * 1024; // [1024][384] n-major (tf32 dn)
static constexpr size_t TOTALF   = 20 * SZ;

__device__ float g_buf[TOTALF];

// ---------------------------------------------------------------------------
// 1) token-shift mixes
// ---------------------------------------------------------------------------
__global__ void __launch_bounds__(256) mix_kernel(
    const float* __restrict__ x,
    const float* __restrict__ mr, const float* __restrict__ mw,
    const float* __restrict__ mk, const float* __restrict__ mv,
    const float* __restrict__ ma, const float* __restrict__ mg)
{
    int idx = blockIdx.x * 256 + threadIdx.x;
    int c   = idx & (CH - 1);
    int row = idx >> 10;
    int t   = row & 1023;
    float xv = x[idx];
    float lx = (t == 0) ? 0.f : x[idx - CH];
    float dx = lx - xv;
    g_buf[OFF_XR + idx] = fmaf(mr[c], dx, xv);
    g_buf[OFF_XW + idx] = fmaf(mw[c], dx, xv);
    g_buf[OFF_XK + idx] = fmaf(mk[c], dx, xv);
    g_buf[OFF_XV + idx] = fmaf(mv[c], dx, xv);
    g_buf[OFF_XA + idx] = fmaf(ma[c], dx, xv);
    g_buf[OFF_XG + idx] = fmaf(mg[c], dx, xv);
}

// ---------------------------------------------------------------------------
// weight packs
// up: [1024][384] k-major rows (for fp32 up kernel, B[k*NUP+n])
// ---------------------------------------------------------------------------
__global__ void __launch_bounds__(256) pack_up_kernel(
    const float* __restrict__ w1, const float* __restrict__ a1,
    const float* __restrict__ v1, const float* __restrict__ g1)
{
    int idx = blockIdx.x * 256 + threadIdx.x;   // < 1024*384
    if (idx >= 1024 * NUP) return;
    int k = idx / NUP;
    int n = idx - k * NUP;
    float v;
    if      (n < 64)  v = w1[k * 64  + n];
    else if (n < 128) v = a1[k * 64  + (n - 64)];
    else if (n < 160) v = v1[k * 32  + (n - 128)];
    else if (n < 192) v = 0.f;
    else if (n < 352) v = g1[k * 160 + (n - 192)];
    else              v = 0.f;
    g_buf[OFF_WUP + idx] = v;
}

// dn: [1024][384] n-major rows (for tf32 NT dn kernel, B[n*NUP+kk])
__global__ void __launch_bounds__(256) pack_dn_kernel(
    const float* __restrict__ w2, const float* __restrict__ a2,
    const float* __restrict__ v2, const float* __restrict__ g2)
{
    int idx = blockIdx.x * 256 + threadIdx.x;       // < 1024*384
    if (idx >= 1024 * NUP) return;
    int n  = idx / NUP;
    int kk = idx - n * NUP;
    float v;
    if      (kk < 64)  v = w2[(size_t)kk * 1024 + n];
    else if (kk < 128) v = a2[(size_t)(kk - 64) * 1024 + n];
    else if (kk < 160) v = v2[(size_t)(kk - 128) * 1024 + n];
    else if (kk < 192) v = 0.f;
    else if (kk < 352) v = g2[(size_t)(kk - 192) * 1024 + n];
    else               v = 0.f;
    g_buf[OFF_WDNT + idx] = v;
}

// ---------------------------------------------------------------------------
// tf32 MMA core (NT): C[m,n] = sum_k A[m,k]*B[n,k]
// 128x128 tile, BK=16, 256 threads, warp tile 64x32, double-buffered smem.
// ---------------------------------------------------------------------------
__device__ __forceinline__ uint32_t f2tf32(float f) {
    uint32_t u; asm("cvt.rna.tf32.f32 %0, %1;" : "=r"(u) : "f"(f)); return u;
}

__device__ __forceinline__ void gemm_tf32_core(
    uint32_t (&As)[2][128][20], uint32_t (&Bs)[2][128][20],
    const float* __restrict__ A, int lda,
    const float* __restrict__ B, int ldb,
    float* __restrict__ C, int ldc,
    int K, int m0, int n0)
{
    const int tid  = threadIdx.x;
    const int lane = tid & 31, warp = tid >> 5;
    const int wm = warp >> 2, wn = warp & 3;

    const int lr = tid >> 2;            // 0..63
    const int lc = (tid & 3) * 4;       // 0,4,8,12

    const float* Aptr = A + (size_t)(m0 + lr) * lda + lc;
    const float* Bptr = B + (size_t)(n0 + lr) * ldb + lc;

    float acc[4][4][4];
#pragma unroll
    for (int mt = 0; mt < 4; mt++)
#pragma unroll
        for (int nt = 0; nt < 4; nt++)
#pragma unroll
            for (int r = 0; r < 4; r++) acc[mt][nt][r] = 0.f;

    {
        float4 a0 = *(const float4*)(Aptr);
        float4 a1 = *(const float4*)(Aptr + (size_t)64 * lda);
        float4 b0 = *(const float4*)(Bptr);
        float4 b1 = *(const float4*)(Bptr + (size_t)64 * ldb);
        As[0][lr][lc+0] = f2tf32(a0.x); As[0][lr][lc+1] = f2tf32(a0.y);
        As[0][lr][lc+2] = f2tf32(a0.z); As[0][lr][lc+3] = f2tf32(a0.w);
        As[0][lr+64][lc+0] = f2tf32(a1.x); As[0][lr+64][lc+1] = f2tf32(a1.y);
        As[0][lr+64][lc+2] = f2tf32(a1.z); As[0][lr+64][lc+3] = f2tf32(a1.w);
        Bs[0][lr][lc+0] = f2tf32(b0.x); Bs[0][lr][lc+1] = f2tf32(b0.y);
        Bs[0][lr][lc+2] = f2tf32(b0.z); Bs[0][lr][lc+3] = f2tf32(b0.w);
        Bs[0][lr+64][lc+0] = f2tf32(b1.x); Bs[0][lr+64][lc+1] = f2tf32(b1.y);
        Bs[0][lr+64][lc+2] = f2tf32(b1.z); Bs[0][lr+64][lc+3] = f2tf32(b1.w);
    }
    __syncthreads();

    int buf = 0;
    for (int k0 = 0; k0 < K; k0 += 16) {
        float4 na0, na1, nb0, nb1;
        const bool more = (k0 + 16) < K;
        if (more) {
            na0 = *(const float4*)(Aptr + k0 + 16);
            na1 = *(const float4*)(Aptr + (size_t)64 * lda + k0 + 16);
            nb0 = *(const float4*)(Bptr + k0 + 16);
            nb1 = *(const float4*)(Bptr + (size_t)64 * ldb + k0 + 16);
        }
#pragma unroll
        for (int kk = 0; kk < 2; kk++) {
            uint32_t af[4][4], bf[4][2];
            const int c = kk * 8 + (lane & 3);
#pragma unroll
            for (int mt = 0; mt < 4; mt++) {
                int r = wm * 64 + mt * 16 + (lane >> 2);
                af[mt][0] = As[buf][r    ][c];
                af[mt][1] = As[buf][r + 8][c];
                af[mt][2] = As[buf][r    ][c + 4];
                af[mt][3] = As[buf][r + 8][c + 4];
            }
#pragma unroll
            for (int nt = 0; nt < 4; nt++) {
                int n = wn * 32 + nt * 8 + (lane >> 2);
                bf[nt][0] = Bs[buf][n][c];
                bf[nt][1] = Bs[buf][n][c + 4];
            }
#pragma unroll
            for (int mt = 0; mt < 4; mt++)
#pragma unroll
                for (int nt = 0; nt < 4; nt++) {
                    asm volatile(
                        "mma.sync.aligned.m16n8k8.row.col.f32.tf32.tf32.f32 "
                        "{%0,%1,%2,%3},{%4,%5,%6,%7},{%8,%9},{%0,%1,%2,%3};"
                        : "+f"(acc[mt][nt][0]), "+f"(acc[mt][nt][1]),
                          "+f"(acc[mt][nt][2]), "+f"(acc[mt][nt][3])
                        : "r"(af[mt][0]), "r"(af[mt][1]),
                          "r"(af[mt][2]), "r"(af[mt][3]),
                          "r"(bf[nt][0]), "r"(bf[nt][1]));
                }
        }
        if (more) {
            int nb = buf ^ 1;
            As[nb][lr][lc+0] = f2tf32(na0.x); As[nb][lr][lc+1] = f2tf32(na0.y);
            As[nb][lr][lc+2] = f2tf32(na0.z); As[nb][lr][lc+3] = f2tf32(na0.w);
            As[nb][lr+64][lc+0] = f2tf32(na1.x); As[nb][lr+64][lc+1] = f2tf32(na1.y);
            As[nb][lr+64][lc+2] = f2tf32(na1.z); As[nb][lr+64][lc+3] = f2tf32(na1.w);
            Bs[nb][lr][lc+0] = f2tf32(nb0.x); Bs[nb][lr][lc+1] = f2tf32(nb0.y);
            Bs[nb][lr][lc+2] = f2tf32(nb0.z); Bs[nb][lr][lc+3] = f2tf32(nb0.w);
            Bs[nb][lr+64][lc+0] = f2tf32(nb1.x); Bs[nb][lr+64][lc+1] = f2tf32(nb1.y);
            Bs[nb][lr+64][lc+2] = f2tf32(nb1.z); Bs[nb][lr+64][lc+3] = f2tf32(nb1.w);
        }
        __syncthreads();
        buf ^= 1;
    }

#pragma unroll
    for (int mt = 0; mt < 4; mt++) {
        int row = m0 + wm * 64 + mt * 16 + (lane >> 2);
#pragma unroll
        for (int nt = 0; nt < 4; nt++) {
            int col = n0 + wn * 32 + nt * 8 + (lane & 3) * 2;
            *(float2*)(C + (size_t)row * ldc + col) =
                make_float2(acc[mt][nt][0], acc[mt][nt][1]);
            *(float2*)(C + (size_t)(row + 8) * ldc + col) =
                make_float2(acc[mt][nt][2], acc[mt][nt][3]);
        }
    }
}

// generic wrapper
__global__ void __launch_bounds__(256) gemm_tf32_nt(
    const float* __restrict__ A, int lda,
    const float* __restrict__ B, int ldb,
    float* __restrict__ C, int ldc, int K)
{
    __shared__ uint32_t As[2][128][20];
    __shared__ uint32_t Bs[2][128][20];
    gemm_tf32_core(As, Bs, A, lda, B, ldb, C, ldc, K,
                   blockIdx.y * 128, blockIdx.x * 128);
}

// fused r/k/v projections: grid.x = 24 (3 proj x 8 col tiles)
__global__ void __launch_bounds__(256) gemm_rkv(
    const float* __restrict__ Wr, const float* __restrict__ Wk,
    const float* __restrict__ Wv)
{
    __shared__ uint32_t As[2][128][20];
    __shared__ uint32_t Bs[2][128][20];
    const int p  = blockIdx.x >> 3;
    const int n0 = (blockIdx.x & 7) * 128;
    const float* A = g_buf + ((p == 0) ? OFF_XR : (p == 1) ? OFF_XK : OFF_XV);
    const float* B = (p == 0) ? Wr : (p == 1) ? Wk : Wv;
    float* C = g_buf + OFF_R + (size_t)p * SZ;
    gemm_tf32_core(As, Bs, A, CH, B, CH, C, CH, CH,
                   blockIdx.y * 128, n0);
}

// batched LoRA down-projections: grid.z = 4 (w,a,v,g)
__global__ void __launch_bounds__(256) gemm_dn()
{
    __shared__ uint32_t As[2][128][20];
    __shared__ uint32_t Bs[2][128][20];
    const int z = blockIdx.z;
    const int koff = (z == 0) ? 0 : (z == 1) ? 64 : (z == 2) ? 128 : 192;
    const int Kz   = (z == 0) ? 64 : (z == 1) ? 64 : (z == 2) ? 32 : 160;
    const float* A = g_buf + OFF_H + koff;
    const float* B = g_buf + OFF_WDNT + koff;
    float* C = g_buf + OFF_TW + (size_t)z * SZ;
    gemm_tf32_core(As, Bs, A, NUP, B, NUP, C, CH, Kz,
                   blockIdx.y * 128, blockIdx.x * 128);
}

// ---------------------------------------------------------------------------
// fused LoRA up-projection (fp32, known-correct R2 kernel):
// H[TOK][384] = [tanh(xw@w1) | xa@a1 | xv@v1 | 0 | sigmoid(xg@g1) | pad]
// 64-wide column tiles; A pointer + activation per tile.
// ---------------------------------------------------------------------------
__global__ void __launch_bounds__(256) gemm_up_kernel(
    const float* __restrict__ Aw, const float* __restrict__ Aa,
    const float* __restrict__ Av, const float* __restrict__ Ag)
{
    __shared__ float As[16][68];
    __shared__ float Bs[16][68];
    const int tid = threadIdx.x;
    const int tm = tid >> 4, tn = tid & 15;
    const int m0 = blockIdx.y * 64, n0 = blockIdx.x * 64;

    const int seg = (blockIdx.x == 0) ? 0 : (blockIdx.x == 1) ? 1 :
                    (blockIdx.x == 2) ? 2 : 3;
    const float* A = (seg == 0) ? Aw : (seg == 1) ? Aa : (seg == 2) ? Av : Ag;
    const float* B = g_buf + OFF_WUP;
    float* Cm = g_buf + OFF_H;

    const int lm = tid >> 2;
    const int lk = (tid & 3) * 4;

    float acc[4][4];
#pragma unroll
    for (int i = 0; i < 4; i++)
#pragma unroll
        for (int j = 0; j < 4; j++) acc[i][j] = 0.f;

    for (int k0 = 0; k0 < CH; k0 += 16) {
        float4 av = *(const float4*)(A + (size_t)(m0 + lm) * CH + k0 + lk);
        As[lk + 0][lm] = av.x; As[lk + 1][lm] = av.y;
        As[lk + 2][lm] = av.z; As[lk + 3][lm] = av.w;
        {
            int kk = tid >> 4;
            int nj = (tid & 15) * 4;
            float4 bv = *(const float4*)(B + (size_t)(k0 + kk) * NUP + n0 + nj);
            *(float4*)&Bs[kk][nj] = bv;
        }
        __syncthreads();
#pragma unroll
        for (int k = 0; k < 16; k++) {
            float4 a = *(const float4*)&As[k][tm * 4];
            float4 b = *(const float4*)&Bs[k][tn * 4];
            float ar[4] = {a.x, a.y, a.z, a.w};
            float br[4] = {b.x, b.y, b.z, b.w};
#pragma unroll
            for (int i = 0; i < 4; i++)
#pragma unroll
                for (int j = 0; j < 4; j++)
                    acc[i][j] = fmaf(ar[i], br[j], acc[i][j]);
        }
        __syncthreads();
    }

#pragma unroll
    for (int i = 0; i < 4; i++) {
        int row = m0 + tm * 4 + i;
#pragma unroll
        for (int j = 0; j < 4; j++) {
            int col = n0 + tn * 4 + j;
            float v = acc[i][j];
            if (seg == 0)      v = tanhf(v);
            else if (seg == 3) v = 1.f / (1.f + expf(-v));
            Cm[(size_t)row * NUP + col] = v;
        }
    }
}

// ---------------------------------------------------------------------------
// per-channel epilogue + kk normalize
// ---------------------------------------------------------------------------
__global__ void __launch_bounds__(256) ew_kernel(
    const float* __restrict__ v_first,
    const float* __restrict__ w0, const float* __restrict__ a0,
    const float* __restrict__ v0p, const float* __restrict__ k_k,
    const float* __restrict__ k_a)
{
    int wid  = blockIdx.x * 8 + (threadIdx.x >> 5);
    int lane = threadIdx.x & 31;
    int t = wid >> 4;
    int h = wid & 15;
    int c0 = h * HS + lane * 2;
    size_t base = (size_t)t * CH + c0;

    float2 tw = *(const float2*)(g_buf + OFF_TW + base);
    float2 ta = *(const float2*)(g_buf + OFF_TA + base);
    float2 tv = *(const float2*)(g_buf + OFF_TV + base);
    float2 kv = *(const float2*)(g_buf + OFF_K + base);
    float2 vv = *(const float2*)(g_buf + OFF_V + base);
    float2 vf = *(const float2*)(v_first + base);
    float2 w0v  = *(const float2*)(w0 + c0);
    float2 a0v  = *(const float2*)(a0 + c0);
    float2 v0v  = *(const float2*)(v0p + c0);
    float2 kkv  = *(const float2*)(k_k + c0);
    float2 kav  = *(const float2*)(k_a + c0);

    auto decay = [](float w0c, float twc) {
        float z = -w0c - twc;
        float sp = (z > 20.f) ? z : log1pf(expf(z));
        float w = -sp - 0.5f;
        return expf(-expf(w));
    };
    float wd0 = decay(w0v.x, tw.x), wd1 = decay(w0v.y, tw.y);

    float aa0 = 1.f / (1.f + expf(-(a0v.x + ta.x)));
    float aa1 = 1.f / (1.f + expf(-(a0v.y + ta.y)));

    float sv0 = 1.f / (1.f + expf(-(v0v.x + tv.x)));
    float sv1 = 1.f / (1.f + expf(-(v0v.y + tv.y)));
    float nv0 = vv.x + (vf.x - vv.x) * sv0;
    float nv1 = vv.y + (vf.y - vv.y) * sv1;

    float kk0 = kv.x * kkv.x, kk1 = kv.y * kkv.y;
    float kn0 = kv.x * (1.f + (aa0 - 1.f) * kav.x);
    float kn1 = kv.y * (1.f + (aa1 - 1.f) * kav.y);

    float ss = kk0 * kk0 + kk1 * kk1;
#pragma unroll
    for (int m = 16; m; m >>= 1) ss += __shfl_xor_sync(0xffffffffu, ss, m);
    float inv = 1.f / fmaxf(sqrtf(ss), 1e-12f);
    float ak0 = kk0 * inv, ak1 = kk1 * inv;
    float bk0 = -ak0 * aa0, bk1 = -ak1 * aa1;

    *(float2*)(g_buf + OFF_WDEC + base) = make_float2(wd0, wd1);
    *(float2*)(g_buf + OFF_V    + base) = make_float2(nv0, nv1);
    *(float2*)(g_buf + OFF_K    + base) = make_float2(kn0, kn1);
    *(float2*)(g_buf + OFF_AKK  + base) = make_float2(ak0, ak1);
    *(float2*)(g_buf + OFF_BKK  + base) = make_float2(bk0, bk1);
}

// ---------------------------------------------------------------------------
// recurrence
// ---------------------------------------------------------------------------
__global__ void __launch_bounds__(128) rec_kernel()
{
    const int bh = blockIdx.x >> 2;
    const int rg = blockIdx.x & 3;
    const int b  = bh >> 4;
    const int h  = bh & 15;
    const int tid = threadIdx.x;
    const int rl = tid >> 3;
    const int q  = tid & 7;
    const int i  = rg * 16 + rl;
    const int j0 = q * 8;

    __shared__ float sh[6][16][64];

    const size_t base = ((size_t)b * 1024) * CH + (size_t)h * HS;
    const float* pr = g_buf + OFF_R    + base;
    const float* pw = g_buf + OFF_WDEC + base;
    const float* pk = g_buf + OFF_K    + base;
    const float* pv = g_buf + OFF_V    + base;
    const float* pa = g_buf + OFF_AKK  + base;
    const float* pb = g_buf + OFF_BKK  + base;
    float*       py = g_buf + OFF_Y    + base;

    float s[8];
#pragma unroll
    for (int jj = 0; jj < 8; jj++) s[jj] = 0.f;

    for (int t0 = 0; t0 < 1024; t0 += 16) {
        __syncthreads();
#pragma unroll
        for (int arr = 0; arr < 6; arr++) {
            const float* src = (arr == 0) ? pr : (arr == 1) ? pw :
                               (arr == 2) ? pk : (arr == 3) ? pv :
                               (arr == 4) ? pa : pb;
#pragma unroll
            for (int rr = 0; rr < 2; rr++) {
                int idx = tid + 128 * rr;
                int st = idx >> 4;
                int sg = idx & 15;
                *(float4*)&sh[arr][st][sg * 4] =
                    *(const float4*)(src + (size_t)(t0 + st) * CH + sg * 4);
            }
        }
        __syncthreads();

        for (int tt = 0; tt < 16; tt++) {
            float4 a4a = *(const float4*)&sh[4][tt][j0];
            float4 a4b = *(const float4*)&sh[4][tt][j0 + 4];
            float a_[8] = {a4a.x, a4a.y, a4a.z, a4a.w, a4b.x, a4b.y, a4b.z, a4b.w};

            float sa0 = fmaf(s[0], a_[0], fmaf(s[2], a_[2], fmaf(s[4], a_[4], s[6] * a_[6])));
            float sa1 = fmaf(s[1], a_[1], fmaf(s[3], a_[3], fmaf(s[5], a_[5], s[7] * a_[7])));
            float sa = sa0 + sa1;
            sa += __shfl_xor_sync(0xffffffffu, sa, 1);
            sa += __shfl_xor_sync(0xffffffffu, sa, 2);
            sa += __shfl_xor_sync(0xffffffffu, sa, 4);

            float vi = sh[3][tt][i];

            float4 w4a = *(const float4*)&sh[1][tt][j0];
            float4 w4b = *(const float4*)&sh[1][tt][j0 + 4];
            float4 k4a = *(const float4*)&sh[2][tt][j0];
            float4 k4b = *(const float4*)&sh[2][tt][j0 + 4];
            float4 b4a = *(const float4*)&sh[5][tt][j0];
            float4 b4b = *(const float4*)&sh[5][tt][j0 + 4];
            float4 r4a = *(const float4*)&sh[0][tt][j0];
            float4 r4b = *(const float4*)&sh[0][tt][j0 + 4];
            float w_[8] = {w4a.x, w4a.y, w4a.z, w4a.w, w4b.x, w4b.y, w4b.z, w4b.w};
            float k_[8] = {k4a.x, k4a.y, k4a.z, k4a.w, k4b.x, k4b.y, k4b.z, k4b.w};
            float b_[8] = {b4a.x, b4a.y, b4a.z, b4a.w, b4b.x, b4b.y, b4b.z, b4b.w};
            float r_[8] = {r4a.x, r4a.y, r4a.z, r4a.w, r4b.x, r4b.y, r4b.z, r4b.w};

            float y0 = 0.f, y1 = 0.f;
#pragma unroll
            for (int jj = 0; jj < 8; jj++) {
                float ns = fmaf(sa, b_[jj], fmaf(vi, k_[jj], s[jj] * w_[jj]));
                s[jj] = ns;
                if (jj & 1) y1 = fmaf(ns, r_[jj], y1);
                else        y0 = fmaf(ns, r_[jj], y0);
            }
            float y = y0 + y1;
            y += __shfl_xor_sync(0xffffffffu, y, 1);
            y += __shfl_xor_sync(0xffffffffu, y, 2);
            y += __shfl_xor_sync(0xffffffffu, y, 4);
            if (q == 0) py[(size_t)(t0 + tt) * CH + i] = y;
        }
    }
}

// ---------------------------------------------------------------------------
// GroupNorm + bonus + gate
// ---------------------------------------------------------------------------
__global__ void __launch_bounds__(256) post_kernel(
    const float* __restrict__ r_k,
    const float* __restrict__ gn_w, const float* __restrict__ gn_b)
{
    int wid  = blockIdx.x * 8 + (threadIdx.x >> 5);
    int lane = threadIdx.x & 31;
    int t = wid >> 4;
    int h = wid & 15;
    int c0 = h * HS + lane * 2;
    size_t base = (size_t)t * CH + c0;

    float2 yv = *(const float2*)(g_buf + OFF_Y + base);
    float2 rv = *(const float2*)(g_buf + OFF_R + base);
    float2 kv = *(const float2*)(g_buf + OFF_K + base);
    float2 vv = *(const float2*)(g_buf + OFF_V + base);
    float2 gv = *(const float2*)(g_buf + OFF_GATE + base);
    float2 rk = *(const float2*)(r_k + c0);

    float s1 = yv.x + yv.y;
    float s2 = yv.x * yv.x + yv.y * yv.y;
    float s3 = rv.x * kv.x * rk.x + rv.y * kv.y * rk.y;
#pragma unroll
    for (int m = 16; m; m >>= 1) {
        s1 += __shfl_xor_sync(0xffffffffu, s1, m);
        s2 += __shfl_xor_sync(0xffffffffu, s2, m);
        s3 += __shfl_xor_sync(0xffffffffu, s3, m);
    }
    float mu  = s1 * (1.f / 64.f);
    float var = s2 * (1.f / 64.f) - mu * mu;
    float rstd = rsqrtf(var + 0.00064f);

    float2 gw = *(const float2*)(gn_w + c0);
    float2 gb = *(const float2*)(gn_b + c0);
    float o0 = (fmaf((yv.x - mu) * rstd, gw.x, gb.x) + s3 * vv.x) * gv.x;
    float o1 = (fmaf((yv.y - mu) * rstd, gw.y, gb.y) + s3 * vv.y) * gv.y;
    *(float2*)(g_buf + OFF_YP + base) = make_float2(o0, o1);
}

// ---------------------------------------------------------------------------
extern "C" void kernel_launch(void* const* d_in, const int* in_sizes, int n_in,
                              void* d_out, int out_size)
{
    (void)in_sizes; (void)n_in; (void)out_size;
    float* buf = nullptr;
    cudaGetSymbolAddress((void**)&buf, g_buf);

    const float* x    = (const float*)d_in[0];
    const float* vfir = (const float*)d_in[1];
    const float* x_r  = (const float*)d_in[2];
    const float* x_w  = (const float*)d_in[3];
    const float* x_k  = (const float*)d_in[4];
    const float* x_v  = (const float*)d_in[5];
    const float* x_a  = (const float*)d_in[6];
    const float* x_g  = (const float*)d_in[7];
    const float* w0   = (const float*)d_in[8];
    const float* w1   = (const float*)d_in[9];
    const float* w2   = (const float*)d_in[10];
    const float* a0   = (const float*)d_in[11];
    const float* a1   = (const float*)d_in[12];
    const float* a2   = (const float*)d_in[13];
    const float* v0p  = (const float*)d_in[14];
    const float* v1   = (const float*)d_in[15];
    const float* v2   = (const float*)d_in[16];
    const float* g1   = (const float*)d_in[17];
    const float* g2   = (const float*)d_in[18];
    const float* k_k  = (const float*)d_in[19];
    const float* k_a  = (const float*)d_in[20];
    const float* r_k  = (const float*)d_in[21];
    const float* W_r  = (const float*)d_in[22];
    const float* W_k  = (const float*)d_in[23];
    const float* W_v  = (const float*)d_in[24];
    const float* W_o  = (const float*)d_in[25];
    const float* gn_w = (const float*)d_in[26];
    const float* gn_b = (const float*)d_in[27];
    float* out = (float*)d_out;

    // 1) token-shift mixes + weight packs
    mix_kernel<<<(int)(SZ / 256), 256>>>(x, x_r, x_w, x_k, x_v, x_a, x_g);
    pack_up_kernel<<<(1024 * NUP + 255) / 256, 256>>>(w1, a1, v1, g1);
    pack_dn_kernel<<<(1024 * NUP + 255) / 256, 256>>>(w2, a2, v2, g2);

    // 2) fused r/k/v projections (tf32 MMA), one launch
    gemm_rkv<<<dim3(24, TOK / 128), 256>>>(W_r, W_k, W_v);

    // 3) fused LoRA up-projection (fp32, per-segment A + activation)
    gemm_up_kernel<<<dim3(NUP / 64, TOK / 64), 256>>>(
        buf + OFF_XW, buf + OFF_XA, buf + OFF_XV, buf + OFF_XG);

    // 4) batched LoRA down-projections (tf32 MMA), one launch
    gemm_dn<<<dim3(CH / 128, TOK / 128, 4), 256>>>();

    // 5) per-channel epilogue + kk normalize
    ew_kernel<<<TOK * NH / 8, 256>>>(vfir, w0, a0, v0p, k_k, k_a);

    // 6) recurrence
    rec_kernel<<<256, 128>>>();

    // 7) groupnorm + bonus + gate
    post_kernel<<<TOK * NH / 8, 256>>>(r_k, gn_w, gn_b);

    // 8) output projection (tf32 MMA) into d_out
    gemm_tf32_nt<<<dim3(CH / 128, TOK / 128), 256>>>(
        buf + OFF_YP, CH, W_o, CH, out, CH, CH);
}